// round 5
// baseline (speedup 1.0000x reference)
#include <cuda_runtime.h>
#include <cuda_fp16.h>
#include <cstdint>
#include <math.h>

// ============================================================================
// ChessNNUE fused kernel, sm_103-compatible (mma.sync fp16 + ldmatrix + cp.async)
//   tiny prep: fp32 -> fp16 for ft_w, l1_w only (features converted in-kernel)
//   main: resident-A (64x768 fp16 w+b in smem, converted from fp32 on load)
//         feat@ft_w^T + ftb -> stm mix -> clip -> l1 via mma -> l2 -> l3 -> sigmoid
//   512 thr, 4Mx4N warp grid, ldmatrix.x4 frags, 3-buffer ft pipe, 1 sync/tile
// ============================================================================

static constexpr int KDIM = 768;
static constexpr int HID  = 1024;
static constexpr int TILEM = 64;        // batch rows per CTA
static constexpr int NTHREADS = 512;
static constexpr int KT_PER_CHUNK = 12; // 768 / 64
static constexpr int NCHUNKS = 16;      // 1024 / 64
static constexpr int NTILES = NCHUNKS * KT_PER_CHUNK; // 192

// ---- device scratch ----
__device__ __align__(128) __half g_ftw_h[(size_t)HID * KDIM];
__device__ __align__(128) __half g_l1wh[8 * 2 * HID];

// ---- smem layout (byte offsets; dynamic smem base is 16B-aligned) ----
static constexpr uint32_t A_STRIDE_B = 776 * 2;              // 1552 B/row (+16B pad)
static constexpr uint32_t A_BYTES    = TILEM * A_STRIDE_B;   // 99328
static constexpr uint32_t OFF_AW     = 0;
static constexpr uint32_t OFF_AB     = A_BYTES;              // 99328
static constexpr uint32_t FT_STRIDE  = 72 * 2;               // 144 B/row
static constexpr uint32_t FT_TILE    = 64 * FT_STRIDE;       // 9216
static constexpr uint32_t OFF_FT     = 2 * A_BYTES;          // 198656 (3 buffers)
static constexpr uint32_t OFF_FTB    = OFF_FT + 3 * FT_TILE; // 226304
static constexpr uint32_t SMEM_DYN   = OFF_FTB + HID * 4;    // 230400 (<= 232448)
// sred (64x8x4 x4 groups = 8KB) aliases OFF_FT after the mainloop drains.

// ---------------------------------------------------------------------------
__device__ __forceinline__ uint32_t smem_u32(const void* p) {
    uint32_t a;
    asm("{ .reg .u64 t; cvta.to.shared.u64 t, %1; cvt.u32.u64 %0, t; }" : "=r"(a) : "l"(p));
    return a;
}
__device__ __forceinline__ void cp16(uint32_t dst, const void* src) {
    asm volatile("cp.async.cg.shared.global [%0], [%1], 16;" :: "r"(dst), "l"(src));
}
#define CP_COMMIT()  asm volatile("cp.async.commit_group;" ::: "memory")
#define CP_WAIT(n)   asm volatile("cp.async.wait_group %0;" :: "n"(n) : "memory")

__device__ __forceinline__ void ldsm4(uint32_t& r0, uint32_t& r1, uint32_t& r2,
                                      uint32_t& r3, uint32_t addr) {
    asm volatile("ldmatrix.sync.aligned.m8n8.x4.shared.b16 {%0,%1,%2,%3}, [%4];"
                 : "=r"(r0), "=r"(r1), "=r"(r2), "=r"(r3) : "r"(addr));
}
__device__ __forceinline__ void mma_f16(float c[4], uint32_t a0, uint32_t a1,
                                        uint32_t a2, uint32_t a3,
                                        uint32_t b0, uint32_t b1) {
    asm volatile(
        "mma.sync.aligned.m16n8k16.row.col.f32.f16.f16.f32 "
        "{%0,%1,%2,%3}, {%4,%5,%6,%7}, {%8,%9}, {%0,%1,%2,%3};\n"
        : "+f"(c[0]), "+f"(c[1]), "+f"(c[2]), "+f"(c[3])
        : "r"(a0), "r"(a1), "r"(a2), "r"(a3), "r"(b0), "r"(b1));
}
__device__ __forceinline__ float clip01(float x) {
    return fminf(fmaxf(x, 0.0f), 1.0f);
}
__device__ __forceinline__ uint32_t pack_h2(float lo, float hi) {
    __half2 v = __floats2half2_rn(lo, hi);
    return *reinterpret_cast<uint32_t*>(&v);
}

// ---------------------------------------------------------------------------
// tiny prep: fp32 -> fp16 for ft_w and l1_w (features are converted in-kernel)
// ---------------------------------------------------------------------------
__global__ void nnue_prep(const float* __restrict__ fw, const float* __restrict__ l1w) {
    int i0 = blockIdx.x * blockDim.x + threadIdx.x;
    int stride = gridDim.x * blockDim.x;
    __half2* fdst = reinterpret_cast<__half2*>(g_ftw_h);
    __half2* ldst = reinterpret_cast<__half2*>(g_l1wh);
    const float2* fsrc = reinterpret_cast<const float2*>(fw);
    const float2* lsrc = reinterpret_cast<const float2*>(l1w);
    for (int j = i0; j < HID * KDIM / 2; j += stride) {
        float2 a = fsrc[j]; fdst[j] = __floats2half2_rn(a.x, a.y);
    }
    for (int j = i0; j < 8 * 2 * HID / 2; j += stride) {
        float2 a = lsrc[j]; ldst[j] = __floats2half2_rn(a.x, a.y);
    }
}

// ---------------------------------------------------------------------------
// main fused kernel
// ---------------------------------------------------------------------------
__global__ __launch_bounds__(NTHREADS, 1) void nnue_main(
    const float* __restrict__ white, const float* __restrict__ black,
    const float* __restrict__ stm, const float* __restrict__ ftb,
    const float* __restrict__ l1b, const float* __restrict__ l2w,
    const float* __restrict__ l2b, const float* __restrict__ l3w,
    const float* __restrict__ l3b, float* __restrict__ out, int B) {
    extern __shared__ char smc[];
    const uint32_t sb = smem_u32(smc);

    const int tid = threadIdx.x;
    const int lane = tid & 31;
    const int wid = tid >> 5;
    const int warpM = wid & 3;   // rows warpM*16 .. +15
    const int warpN = wid >> 2;  // cols warpN*16 .. +15 within 64-chunk
    const int row0 = blockIdx.x * TILEM;

    // ---- kick off async ft staging (ftb + ft tiles 0,1) ----
    if (tid < 256) cp16(sb + OFF_FTB + tid * 16, ftb + tid * 4);
    {   // tile 0: n0=0, k0=0 ; tile 1: n0=0, k0=64   (512 x 16B groups each)
        int r = tid >> 3, c = tid & 7;
        cp16(sb + OFF_FT + 0 * FT_TILE + r * FT_STRIDE + c * 16,
             g_ftw_h + (size_t)r * KDIM + 0 + c * 8);
        CP_COMMIT();   // group: ftb + tile0
        cp16(sb + OFF_FT + 1 * FT_TILE + r * FT_STRIDE + c * 16,
             g_ftw_h + (size_t)r * KDIM + 64 + c * 8);
        CP_COMMIT();   // group: tile1
    }

    // ---- stage resident A: fp32 LDG -> fp16 STS (w and b, 64x768 each) ----
    {
        const int r = tid >> 3, cb = tid & 7;
        const float* wsrc = white + (size_t)(row0 + r) * KDIM;
        const float* bsrc = black + (size_t)(row0 + r) * KDIM;
        char* wdst = smc + OFF_AW + r * A_STRIDE_B;
        char* bdst = smc + OFF_AB + r * A_STRIDE_B;
#pragma unroll
        for (int it = 0; it < 12; it++) {
            const int c = cb + it * 8;   // 16B fp16 group index (0..95)
            float4 x = *reinterpret_cast<const float4*>(wsrc + c * 8);
            float4 y = *reinterpret_cast<const float4*>(wsrc + c * 8 + 4);
            uint4 v;
            v.x = pack_h2(x.x, x.y); v.y = pack_h2(x.z, x.w);
            v.z = pack_h2(y.x, y.y); v.w = pack_h2(y.z, y.w);
            *reinterpret_cast<uint4*>(wdst + c * 16) = v;
            float4 p = *reinterpret_cast<const float4*>(bsrc + c * 8);
            float4 q = *reinterpret_cast<const float4*>(bsrc + c * 8 + 4);
            uint4 u;
            u.x = pack_h2(p.x, p.y); u.y = pack_h2(p.z, p.w);
            u.z = pack_h2(q.x, q.y); u.w = pack_h2(q.z, q.w);
            *reinterpret_cast<uint4*>(bdst + c * 16) = u;
        }
    }

    const float stm_lo = stm[row0 + warpM * 16 + (lane >> 2)];
    const float stm_hi = stm[row0 + warpM * 16 + (lane >> 2) + 8];

    // ldmatrix base addresses (k-invariant parts)
    const uint32_t awA = sb + OFF_AW + (warpM * 16 + (lane & 15)) * A_STRIDE_B +
                         (lane >> 4) * 16;
    const uint32_t abA = awA + (OFF_AB - OFF_AW);
    const uint32_t btA = (warpN * 16 + ((lane >> 4) << 3) + (lane & 7)) * FT_STRIDE +
                         ((lane >> 3) & 1) * 16;

    float wacc[2][4] = {}, bacc[2][4] = {}, sacc[4] = {};

    for (int t = 0; t < NTILES; t++) {
        __syncthreads();   // all warps done with tile t-1 (buffer (t+2)%3 free)
        if (t + 2 < NTILES) {
            const int nt = t + 2;
            const int n0 = (nt / KT_PER_CHUNK) * 64, k0 = (nt % KT_PER_CHUNK) * 64;
            int r = tid >> 3, c = tid & 7;
            cp16(sb + OFF_FT + (nt % 3) * FT_TILE + r * FT_STRIDE + c * 16,
                 g_ftw_h + (size_t)(n0 + r) * KDIM + k0 + c * 8);
        }
        CP_COMMIT();
        CP_WAIT(2);        // tile t's group complete

        const uint32_t bt = sb + OFF_FT + (t % 3) * FT_TILE + btA;
        const uint32_t ak = (uint32_t)((t % KT_PER_CHUNK) * 64) * 2;
#pragma unroll
        for (int ks = 0; ks < 4; ks++) {
            uint32_t aw0, aw1, aw2, aw3, ab0, ab1, ab2, ab3, b0, b1, b2, b3;
            ldsm4(aw0, aw1, aw2, aw3, awA + ak + ks * 32);
            ldsm4(ab0, ab1, ab2, ab3, abA + ak + ks * 32);
            ldsm4(b0, b1, b2, b3, bt + ks * 32);
            mma_f16(wacc[0], aw0, aw1, aw2, aw3, b0, b1);
            mma_f16(wacc[1], aw0, aw1, aw2, aw3, b2, b3);
            mma_f16(bacc[0], ab0, ab1, ab2, ab3, b0, b1);
            mma_f16(bacc[1], ab0, ab1, ab2, ab3, b2, b3);
        }

        // ---- per-chunk epilogue: +ftb, stm mix, clip, l1 partial via mma ----
        if ((t % KT_PER_CHUNK) == KT_PER_CHUNK - 1) {
            const int chunk = t / KT_PER_CHUNK;
            uint32_t A1[4], A2[4];
#pragma unroll
            for (int h = 0; h < 2; h++) {    // h = n-subtile (8 cols)
                const int nidx = chunk * 64 + warpN * 16 + h * 8 + 2 * (lane & 3);
                const float2 fb = *reinterpret_cast<const float2*>(smc + OFF_FTB + nidx * 4);
                float a1v[4], a2v[4];
#pragma unroll
                for (int j = 0; j < 4; j++) {
                    const float fbv = (j & 1) ? fb.y : fb.x;
                    const float sv = (j < 2) ? stm_lo : stm_hi;
                    const float wv = wacc[h][j] + fbv;
                    const float bv = bacc[h][j] + fbv;
                    a1v[j] = clip01(sv * wv + (1.0f - sv) * bv);
                    a2v[j] = clip01(sv * bv + (1.0f - sv) * wv);
                }
                A1[h * 2 + 0] = pack_h2(a1v[0], a1v[1]);
                A1[h * 2 + 1] = pack_h2(a1v[2], a1v[3]);
                A2[h * 2 + 0] = pack_h2(a2v[0], a2v[1]);
                A2[h * 2 + 1] = pack_h2(a2v[2], a2v[3]);
                wacc[h][0] = wacc[h][1] = wacc[h][2] = wacc[h][3] = 0.0f;
                bacc[h][0] = bacc[h][1] = bacc[h][2] = bacc[h][3] = 0.0f;
            }
            const int kcol = chunk * 64 + warpN * 16 + 2 * (lane & 3);
            const __half* bp = g_l1wh + (size_t)(lane >> 2) * (2 * HID) + kcol;
            uint32_t B10 = *reinterpret_cast<const uint32_t*>(bp);
            uint32_t B11 = *reinterpret_cast<const uint32_t*>(bp + 8);
            uint32_t B20 = *reinterpret_cast<const uint32_t*>(bp + HID);
            uint32_t B21 = *reinterpret_cast<const uint32_t*>(bp + HID + 8);
            mma_f16(sacc, A1[0], A1[1], A1[2], A1[3], B10, B11);
            mma_f16(sacc, A2[0], A2[1], A2[2], A2[3], B20, B21);
        }
    }

    // ---- reduce l1 partials across 4 warpN groups (sred aliases ft area) ----
    __syncthreads();
    float* sred = reinterpret_cast<float*>(smc + OFF_FT) + warpN * (TILEM * 8);
    {
        const int rlo = warpM * 16 + (lane >> 2);
        const int o0 = 2 * (lane & 3);
        sred[rlo * 8 + o0] = sacc[0];
        sred[rlo * 8 + o0 + 1] = sacc[1];
        sred[(rlo + 8) * 8 + o0] = sacc[2];
        sred[(rlo + 8) * 8 + o0 + 1] = sacc[3];
    }
    __syncthreads();

    if (tid < TILEM) {
        const float* s0 = reinterpret_cast<const float*>(smc + OFF_FT);
        float l2x[8];
#pragma unroll
        for (int o = 0; o < 8; o++) {
            float s = s0[tid * 8 + o] + s0[512 + tid * 8 + o] +
                      s0[1024 + tid * 8 + o] + s0[1536 + tid * 8 + o];
            l2x[o] = clip01(s + __ldg(&l1b[o]));
        }
        float rawv = __ldg(&l3b[0]);
#pragma unroll 1
        for (int j = 0; j < 32; j++) {
            float tacc = __ldg(&l2b[j]);
#pragma unroll
            for (int o = 0; o < 8; o++) tacc += __ldg(&l2w[j * 8 + o]) * l2x[o];
            rawv += __ldg(&l3w[j]) * clip01(tacc);
        }
        const int gr = row0 + tid;
        out[gr] = 1.0f / (1.0f + expf(-rawv));
        out[B + gr] = rawv;
    }
}

// ---------------------------------------------------------------------------
// launch
// ---------------------------------------------------------------------------
extern "C" void kernel_launch(void* const* d_in, const int* in_sizes, int n_in,
                              void* d_out, int out_size) {
    const float* white = (const float*)d_in[0];
    const float* black = (const float*)d_in[1];
    const float* stm   = (const float*)d_in[2];
    const float* ftw   = (const float*)d_in[3];
    const float* ftb   = (const float*)d_in[4];
    const float* l1w   = (const float*)d_in[5];
    const float* l1b   = (const float*)d_in[6];
    const float* l2w   = (const float*)d_in[7];
    const float* l2b   = (const float*)d_in[8];
    const float* l3w   = (const float*)d_in[9];
    const float* l3b   = (const float*)d_in[10];
    float* out = (float*)d_out;

    const int B = in_sizes[2];  // stm element count

    nnue_prep<<<512, 256>>>(ftw, l1w);

    static int configured = 0;
    if (!configured) {
        cudaFuncSetAttribute(nnue_main, cudaFuncAttributeMaxDynamicSharedMemorySize,
                             SMEM_DYN);
        configured = 1;
    }
    nnue_main<<<B / TILEM, NTHREADS, SMEM_DYN>>>(white, black, stm, ftb, l1b,
                                                 l2w, l2b, l3w, l3b, out, B);
}

// round 8
// speedup vs baseline: 1.1839x; 1.1839x over previous
#include <cuda_runtime.h>
#include <cuda_fp16.h>
#include <cstdint>
#include <math.h>

// ============================================================================
// ChessNNUE fused kernel (sm_103-compatible: mma.sync fp16 + ldmatrix + cp.async)
//   8 warps = 4M x 2N, warp tile = 16 rows x 32 N (w+b) -- traffic-optimal
//   resident-A (w+b feats fp16, padded rows), 3-buffer ft_w cp.async pipe
//   ldmatrix fragments (validated mapping), software-pipelined frags
//   chunk ends: +ftb, stm mix, clip -> l1 via mma ; tail: l2 -> l3 -> sigmoid
// ============================================================================

static constexpr int KDIM = 768;
static constexpr int HID  = 1024;
static constexpr int TILEM = 64;
static constexpr int NTHREADS = 256;
static constexpr int KT_PER_CHUNK = 12;
static constexpr int NCHUNKS = 16;
static constexpr int NTILES = NCHUNKS * KT_PER_CHUNK;  // 192

__device__ __align__(128) __half g_ftw_h[(size_t)HID * KDIM];
__device__ __align__(128) __half g_l1wh[8 * 2 * HID];

// ---- smem layout ----
static constexpr uint32_t A_STRIDE_B = 776 * 2;              // 1552 B/row (97x16B)
static constexpr uint32_t A_BYTES    = TILEM * A_STRIDE_B;   // 99328
static constexpr uint32_t OFF_AW     = 0;
static constexpr uint32_t OFF_AB     = A_BYTES;              // 99328
static constexpr uint32_t FT_STRIDE  = 72 * 2;               // 144 B/row (9x16B)
static constexpr uint32_t FT_TILE    = 64 * FT_STRIDE;       // 9216
static constexpr uint32_t OFF_FT     = 2 * A_BYTES;          // 198656 (3 buffers)
static constexpr uint32_t SMEM_DYN   = OFF_FT + 3 * FT_TILE; // 226304 (<= 232448)
// sred (2 x 64 x 8 fp32 = 4KB) aliases OFF_FT after the mainloop drains.

// ---------------------------------------------------------------------------
__device__ __forceinline__ uint32_t smem_u32(const void* p) {
    uint32_t a;
    asm("{ .reg .u64 t; cvta.to.shared.u64 t, %1; cvt.u32.u64 %0, t; }" : "=r"(a) : "l"(p));
    return a;
}
__device__ __forceinline__ void cp16(uint32_t dst, const void* src) {
    asm volatile("cp.async.cg.shared.global [%0], [%1], 16;" :: "r"(dst), "l"(src));
}
#define CP_COMMIT()  asm volatile("cp.async.commit_group;" ::: "memory")
#define CP_WAIT(n)   asm volatile("cp.async.wait_group %0;" :: "n"(n) : "memory")

__device__ __forceinline__ void ldsm4(uint32_t& r0, uint32_t& r1, uint32_t& r2,
                                      uint32_t& r3, uint32_t addr) {
    asm volatile("ldmatrix.sync.aligned.m8n8.x4.shared.b16 {%0,%1,%2,%3}, [%4];"
                 : "=r"(r0), "=r"(r1), "=r"(r2), "=r"(r3) : "r"(addr));
}
__device__ __forceinline__ void mma_f16(float c[4], uint32_t a0, uint32_t a1,
                                        uint32_t a2, uint32_t a3,
                                        uint32_t b0, uint32_t b1) {
    asm volatile(
        "mma.sync.aligned.m16n8k16.row.col.f32.f16.f16.f32 "
        "{%0,%1,%2,%3}, {%4,%5,%6,%7}, {%8,%9}, {%0,%1,%2,%3};\n"
        : "+f"(c[0]), "+f"(c[1]), "+f"(c[2]), "+f"(c[3])
        : "r"(a0), "r"(a1), "r"(a2), "r"(a3), "r"(b0), "r"(b1));
}
__device__ __forceinline__ float clip01(float x) {
    return fminf(fmaxf(x, 0.0f), 1.0f);
}
__device__ __forceinline__ uint32_t pack_h2(float lo, float hi) {
    __half2 v = __floats2half2_rn(lo, hi);
    return *reinterpret_cast<uint32_t*>(&v);
}

// ---------------------------------------------------------------------------
// prep: fp32 -> fp16 for ft_w and l1_w
// ---------------------------------------------------------------------------
__global__ void nnue_prep(const float* __restrict__ fw, const float* __restrict__ l1w) {
    int i0 = blockIdx.x * blockDim.x + threadIdx.x;
    int stride = gridDim.x * blockDim.x;
    __half2* fdst = reinterpret_cast<__half2*>(g_ftw_h);
    __half2* ldst = reinterpret_cast<__half2*>(g_l1wh);
    const float2* fsrc = reinterpret_cast<const float2*>(fw);
    const float2* lsrc = reinterpret_cast<const float2*>(l1w);
    for (int j = i0; j < HID * KDIM / 2; j += stride) {
        float2 a = fsrc[j]; fdst[j] = __floats2half2_rn(a.x, a.y);
    }
    for (int j = i0; j < 8 * 2 * HID / 2; j += stride) {
        float2 a = lsrc[j]; ldst[j] = __floats2half2_rn(a.x, a.y);
    }
}

// ---------------------------------------------------------------------------
// main fused kernel
// ---------------------------------------------------------------------------
__global__ __launch_bounds__(NTHREADS, 1) void nnue_main(
    const float* __restrict__ white, const float* __restrict__ black,
    const float* __restrict__ stm, const float* __restrict__ ftb,
    const float* __restrict__ l1b, const float* __restrict__ l2w,
    const float* __restrict__ l2b, const float* __restrict__ l3w,
    const float* __restrict__ l3b, float* __restrict__ out, int B) {
    extern __shared__ char smc[];
    const uint32_t sb = smem_u32(smc);

    const int tid = threadIdx.x;
    const int lane = tid & 31;
    const int wid = tid >> 5;
    const int warpM = wid & 3;      // rows warpM*16 .. +15
    const int warpN = wid >> 2;     // cols warpN*32 .. +31 within 64-chunk
    const int row0 = blockIdx.x * TILEM;

    // ---- prefetch ft tiles 0,1 (each its own commit group) ----
    {
        int i = tid, r = i >> 3, c = i & 7;     // 512 chunks per tile, 2 per thread
        int i2 = tid + 256, r2 = i2 >> 3, c2 = i2 & 7;
        cp16(sb + OFF_FT + r * FT_STRIDE + c * 16, g_ftw_h + (size_t)r * KDIM + c * 8);
        cp16(sb + OFF_FT + r2 * FT_STRIDE + c2 * 16, g_ftw_h + (size_t)r2 * KDIM + c2 * 8);
        CP_COMMIT();   // tile 0
        cp16(sb + OFF_FT + FT_TILE + r * FT_STRIDE + c * 16,
             g_ftw_h + (size_t)r * KDIM + 64 + c * 8);
        cp16(sb + OFF_FT + FT_TILE + r2 * FT_STRIDE + c2 * 16,
             g_ftw_h + (size_t)r2 * KDIM + 64 + c2 * 8);
        CP_COMMIT();   // tile 1
    }

    // ---- stage resident A: fp32 LDG -> fp16 STS (w and b, 64x768 each) ----
    {
        const int r = tid >> 2, cb = tid & 3;
        const float* wsrc = white + (size_t)(row0 + r) * KDIM;
        const float* bsrc = black + (size_t)(row0 + r) * KDIM;
        char* wdst = smc + OFF_AW + r * A_STRIDE_B;
        char* bdst = smc + OFF_AB + r * A_STRIDE_B;
#pragma unroll
        for (int it = 0; it < 24; it++) {
            const int c = cb + it * 4;   // 16B fp16 group index (0..95)
            float4 x = *reinterpret_cast<const float4*>(wsrc + c * 8);
            float4 y = *reinterpret_cast<const float4*>(wsrc + c * 8 + 4);
            uint4 v;
            v.x = pack_h2(x.x, x.y); v.y = pack_h2(x.z, x.w);
            v.z = pack_h2(y.x, y.y); v.w = pack_h2(y.z, y.w);
            *reinterpret_cast<uint4*>(wdst + c * 16) = v;
            float4 p = *reinterpret_cast<const float4*>(bsrc + c * 8);
            float4 q = *reinterpret_cast<const float4*>(bsrc + c * 8 + 4);
            uint4 u;
            u.x = pack_h2(p.x, p.y); u.y = pack_h2(p.z, p.w);
            u.z = pack_h2(q.x, q.y); u.w = pack_h2(q.z, q.w);
            *reinterpret_cast<uint4*>(bdst + c * 16) = u;
        }
    }

    const float stm_lo = stm[row0 + warpM * 16 + (lane >> 2)];
    const float stm_hi = stm[row0 + warpM * 16 + (lane >> 2) + 8];

    // ---- ldmatrix lane addresses (validated mapping from R4-bench) ----
    const uint32_t awA = sb + OFF_AW + (warpM * 16 + (lane & 15)) * A_STRIDE_B +
                         (lane >> 4) * 16;
    const uint32_t abA = awA + (OFF_AB - OFF_AW);
    const uint32_t btA0 = (uint32_t)(warpN * 32 + ((lane >> 4) << 3) + (lane & 7)) *
                              FT_STRIDE + ((lane >> 3) & 1) * 16;
    const uint32_t btA1 = btA0 + 16 * FT_STRIDE;

    float wacc[4][4] = {}, bacc[4][4] = {}, sacc[4] = {};

    for (int t = 0; t < NTILES; t++) {
        __syncthreads();   // all warps done with tile t-1 -> buffer (t+2)%3 free
        if (t + 2 < NTILES) {
            const int nt = t + 2;
            const int n0 = (nt / KT_PER_CHUNK) * 64, k0n = (nt % KT_PER_CHUNK) * 64;
            const uint32_t db = sb + OFF_FT + (uint32_t)(nt % 3) * FT_TILE;
            int i = tid, r = i >> 3, c = i & 7;
            int i2 = tid + 256, r2 = i2 >> 3, c2 = i2 & 7;
            cp16(db + r * FT_STRIDE + c * 16,
                 g_ftw_h + (size_t)(n0 + r) * KDIM + k0n + c * 8);
            cp16(db + r2 * FT_STRIDE + c2 * 16,
                 g_ftw_h + (size_t)(n0 + r2) * KDIM + k0n + c2 * 8);
        }
        CP_COMMIT();
        CP_WAIT(2);        // tile t resident (2 newer groups may be pending)

        const uint32_t bt = sb + OFF_FT + (uint32_t)(t % 3) * FT_TILE;
        const uint32_t ak = (uint32_t)((t % KT_PER_CHUNK) * 64) * 2;  // bytes

        // software-pipelined fragments: load ks+1 while mma ks
        uint32_t aw[2][4], ab[2][4], b0f[2][4], b1f[2][4];
        ldsm4(aw[0][0], aw[0][1], aw[0][2], aw[0][3], awA + ak);
        ldsm4(ab[0][0], ab[0][1], ab[0][2], ab[0][3], abA + ak);
        ldsm4(b0f[0][0], b0f[0][1], b0f[0][2], b0f[0][3], bt + btA0);
        ldsm4(b1f[0][0], b1f[0][1], b1f[0][2], b1f[0][3], bt + btA1);
#pragma unroll
        for (int ks = 0; ks < 4; ks++) {
            const int cur = ks & 1, nxt = cur ^ 1;
            if (ks < 3) {
                const uint32_t ko = (uint32_t)(ks + 1) * 32;
                ldsm4(aw[nxt][0], aw[nxt][1], aw[nxt][2], aw[nxt][3], awA + ak + ko);
                ldsm4(ab[nxt][0], ab[nxt][1], ab[nxt][2], ab[nxt][3], abA + ak + ko);
                ldsm4(b0f[nxt][0], b0f[nxt][1], b0f[nxt][2], b0f[nxt][3], bt + btA0 + ko);
                ldsm4(b1f[nxt][0], b1f[nxt][1], b1f[nxt][2], b1f[nxt][3], bt + btA1 + ko);
            }
            mma_f16(wacc[0], aw[cur][0], aw[cur][1], aw[cur][2], aw[cur][3],
                    b0f[cur][0], b0f[cur][1]);
            mma_f16(wacc[1], aw[cur][0], aw[cur][1], aw[cur][2], aw[cur][3],
                    b0f[cur][2], b0f[cur][3]);
            mma_f16(wacc[2], aw[cur][0], aw[cur][1], aw[cur][2], aw[cur][3],
                    b1f[cur][0], b1f[cur][1]);
            mma_f16(wacc[3], aw[cur][0], aw[cur][1], aw[cur][2], aw[cur][3],
                    b1f[cur][2], b1f[cur][3]);
            mma_f16(bacc[0], ab[cur][0], ab[cur][1], ab[cur][2], ab[cur][3],
                    b0f[cur][0], b0f[cur][1]);
            mma_f16(bacc[1], ab[cur][0], ab[cur][1], ab[cur][2], ab[cur][3],
                    b0f[cur][2], b0f[cur][3]);
            mma_f16(bacc[2], ab[cur][0], ab[cur][1], ab[cur][2], ab[cur][3],
                    b1f[cur][0], b1f[cur][1]);
            mma_f16(bacc[3], ab[cur][0], ab[cur][1], ab[cur][2], ab[cur][3],
                    b1f[cur][2], b1f[cur][3]);
        }

        // ---- per-chunk epilogue: +ftb, stm mix, clip, l1 partial via mma ----
        if ((t % KT_PER_CHUNK) == KT_PER_CHUNK - 1) {
            const int chunk = t / KT_PER_CHUNK;
#pragma unroll
            for (int kg = 0; kg < 2; kg++) {
                uint32_t A1[4], A2[4];
#pragma unroll
                for (int h = 0; h < 2; h++) {
                    const int f = kg * 2 + h;
                    const int nidx = chunk * 64 + warpN * 32 + f * 8 + 2 * (lane & 3);
                    const float2 fb = __ldg(reinterpret_cast<const float2*>(ftb + nidx));
                    float a1v[4], a2v[4];
#pragma unroll
                    for (int j = 0; j < 4; j++) {
                        const float fbv = (j & 1) ? fb.y : fb.x;
                        const float sv = (j < 2) ? stm_lo : stm_hi;
                        const float wv = wacc[f][j] + fbv;
                        const float bv = bacc[f][j] + fbv;
                        a1v[j] = clip01(sv * wv + (1.0f - sv) * bv);
                        a2v[j] = clip01(sv * bv + (1.0f - sv) * wv);
                    }
                    A1[h * 2 + 0] = pack_h2(a1v[0], a1v[1]);
                    A1[h * 2 + 1] = pack_h2(a1v[2], a1v[3]);
                    A2[h * 2 + 0] = pack_h2(a2v[0], a2v[1]);
                    A2[h * 2 + 1] = pack_h2(a2v[2], a2v[3]);
                    wacc[f][0] = wacc[f][1] = wacc[f][2] = wacc[f][3] = 0.0f;
                    bacc[f][0] = bacc[f][1] = bacc[f][2] = bacc[f][3] = 0.0f;
                }
                const int kcol = chunk * 64 + warpN * 32 + kg * 16 + 2 * (lane & 3);
                const __half* bp = g_l1wh + (size_t)(lane >> 2) * (2 * HID) + kcol;
                uint32_t B10 = *reinterpret_cast<const uint32_t*>(bp);
                uint32_t B11 = *reinterpret_cast<const uint32_t*>(bp + 8);
                uint32_t B20 = *reinterpret_cast<const uint32_t*>(bp + HID);
                uint32_t B21 = *reinterpret_cast<const uint32_t*>(bp + HID + 8);
                mma_f16(sacc, A1[0], A1[1], A1[2], A1[3], B10, B11);
                mma_f16(sacc, A2[0], A2[1], A2[2], A2[3], B20, B21);
            }
        }
    }

    // ---- reduce l1 partials across 2 warpN groups (sred aliases ft area) ----
    __syncthreads();
    float* sred = reinterpret_cast<float*>(smc + OFF_FT);  // 2 x 64 x 8 floats
    {
        const int rlo = warpM * 16 + (lane >> 2);
        const int o0 = 2 * (lane & 3);
        float* g = sred + warpN * (TILEM * 8);
        g[rlo * 8 + o0] = sacc[0];
        g[rlo * 8 + o0 + 1] = sacc[1];
        g[(rlo + 8) * 8 + o0] = sacc[2];
        g[(rlo + 8) * 8 + o0 + 1] = sacc[3];
    }
    __syncthreads();

    if (tid < TILEM) {
        float l2x[8];
#pragma unroll
        for (int o = 0; o < 8; o++) {
            float s = sred[tid * 8 + o] + sred[TILEM * 8 + tid * 8 + o];
            l2x[o] = clip01(s + __ldg(&l1b[o]));
        }
        float rawv = __ldg(&l3b[0]);
#pragma unroll 1
        for (int j = 0; j < 32; j++) {
            float tacc = __ldg(&l2b[j]);
#pragma unroll
            for (int o = 0; o < 8; o++) tacc += __ldg(&l2w[j * 8 + o]) * l2x[o];
            rawv += __ldg(&l3w[j]) * clip01(tacc);
        }
        const int gr = row0 + tid;
        out[gr] = 1.0f / (1.0f + expf(-rawv));
        out[B + gr] = rawv;
    }
}

// ---------------------------------------------------------------------------
// launch
// ---------------------------------------------------------------------------
extern "C" void kernel_launch(void* const* d_in, const int* in_sizes, int n_in,
                              void* d_out, int out_size) {
    const float* white = (const float*)d_in[0];
    const float* black = (const float*)d_in[1];
    const float* stm   = (const float*)d_in[2];
    const float* ftw   = (const float*)d_in[3];
    const float* ftb   = (const float*)d_in[4];
    const float* l1w   = (const float*)d_in[5];
    const float* l1b   = (const float*)d_in[6];
    const float* l2w   = (const float*)d_in[7];
    const float* l2b   = (const float*)d_in[8];
    const float* l3w   = (const float*)d_in[9];
    const float* l3b   = (const float*)d_in[10];
    float* out = (float*)d_out;

    const int B = in_sizes[2];

    nnue_prep<<<512, 256>>>(ftw, l1w);

    static int configured = 0;
    if (!configured) {
        cudaFuncSetAttribute(nnue_main, cudaFuncAttributeMaxDynamicSharedMemorySize,
                             SMEM_DYN);
        configured = 1;
    }
    nnue_main<<<B / TILEM, NTHREADS, SMEM_DYN>>>(white, black, stm, ftb, l1b,
                                                 l2w, l2b, l3w, l3b, out, B);
}